// round 10
// baseline (speedup 1.0000x reference)
#include <cuda_runtime.h>

// ---------------------------------------------------------------------------
// ScalarDotProductCriticNetworkV8 — multi-kernel SGEMM restructure (R10).
//
// Shapes: B=512, N=16, A=16, OBS=112, D=128, H=64, F_IN=128. M = B*N = 8192.
//
// R10 vs R8/R9 (51us plateau; broadcast-row loops capped at ~2.7 FMA/L1-wf):
//   A1: C[8192x384] = states @ [WkT|WqT|WvT_states]  (64x128 tile, 8x8/thread
//       register blocking -> ~16 FMA per LDS wavefront). Biases folded,
//       q pre-scaled by 1/sqrt(D).
//   A2: avo = tanh(cs + act@Wv_tail), avd = tanh(cs + pol@Wv_tail).
//   A3: [AW1|AdW1] = av @ W1T (same blocking, W1T smem-resident).
//   B : per-batch scores/softmax/SW1/output (reuses R8 P3/P5 code).
// Scratch lives in __device__ globals (24.6MB, L2-resident).
// ---------------------------------------------------------------------------

#define ULL unsigned long long

#define PACK2(d, lo, hi) asm("mov.b64 %0, {%1, %2};" : "=l"(d) : "f"(lo), "f"(hi))
#define UNPACK2(lo, hi, v) asm("mov.b64 {%0, %1}, %2;" : "=f"(lo), "=f"(hi) : "l"(v))
#define FMA2(acc, a, b) asm("fma.rn.f32x2 %0, %1, %2, %0;" : "+l"(acc) : "l"(a), "l"(b))
#define TANHA(y, x) asm("tanh.approx.f32 %0, %1;" : "=f"(y) : "f"(x))

// Weights (pre-transposed) and activations scratch.
__device__ float g_B1[112 * 384];    // [kk][col]: col 0-127 WkT, 128-255 WqT, 256-383 WvT(states part)
__device__ float g_Btail[16 * 128];  // [f][c] = Wv[c][112+f]
__device__ float g_W1T[128 * 64];    // [d][h]
__device__ float g_C[8192 * 384];    // row-major: k | q(scaled+biased) | cs(biased)
__device__ float g_av[8192 * 256];   // avo | avd
__device__ float g_aw[8192 * 128];   // AW1 | AdW1

__global__ void prep(const float* __restrict__ Wk, const float* __restrict__ Wq,
                     const float* __restrict__ Wv, const float* __restrict__ W1) {
    int t = blockIdx.x * blockDim.x + threadIdx.x, S = gridDim.x * blockDim.x;
    for (int i = t; i < 112 * 384; i += S) {
        int kk = i / 384, col = i - kk * 384;
        float v;
        if (col < 128)      v = Wk[col * 112 + kk];
        else if (col < 256) v = Wq[(col - 128) * 112 + kk];
        else                v = Wv[(col - 256) * 128 + kk];
        g_B1[i] = v;
    }
    for (int i = t; i < 16 * 128; i += S) {
        int f = i >> 7, c = i & 127;
        g_Btail[i] = Wv[c * 128 + 112 + f];
    }
    for (int i = t; i < 128 * 64; i += S) {
        int d = i >> 6, h = i & 63;
        g_W1T[i] = W1[h * 128 + d];
    }
}

// ---- A1: C = states @ B1 (+bias, q-scale). grid (128, 3), block 128 ----
__global__ void __launch_bounds__(128) gemm_kqc(
    const float* __restrict__ states, const float* __restrict__ bk,
    const float* __restrict__ bq, const float* __restrict__ bv) {
    __shared__ float As[16][68];     // [kk][row], 64 rows
    __shared__ float Bs[16][128];    // [kk][col]
    const int tid = threadIdx.x;
    const int m0 = blockIdx.x * 64, n0 = blockIdx.y * 128;
    const int tr = tid >> 4, tc = tid & 15;   // 8 row-groups x 16 col-groups
    ULL acc[8][4];
#pragma unroll
    for (int r = 0; r < 8; r++)
#pragma unroll
        for (int c = 0; c < 4; c++) acc[r][c] = 0ull;

    for (int k0 = 0; k0 < 112; k0 += 16) {
        // A chunk [64x16] -> As[kk][row]
#pragma unroll
        for (int w = 0; w < 2; w++) {
            int idx = tid * 2 + w;                 // 0..255
            int row = idx >> 2, kq = (idx & 3) * 4;
            float4 v = *reinterpret_cast<const float4*>(states + (m0 + row) * 112 + k0 + kq);
            As[kq + 0][row] = v.x; As[kq + 1][row] = v.y;
            As[kq + 2][row] = v.z; As[kq + 3][row] = v.w;
        }
        // B chunk [16x128]
#pragma unroll
        for (int w = 0; w < 4; w++) {
            int f4i = w * 128 + tid;               // 0..511
            int row = f4i >> 5, col = (f4i & 31) * 4;
            *reinterpret_cast<float4*>(&Bs[row][col]) =
                *reinterpret_cast<const float4*>(g_B1 + (k0 + row) * 384 + n0 + col);
        }
        __syncthreads();
#pragma unroll
        for (int kk = 0; kk < 16; kk++) {
            float4 a0 = *reinterpret_cast<const float4*>(&As[kk][tr * 8]);
            float4 a1 = *reinterpret_cast<const float4*>(&As[kk][tr * 8 + 4]);
            float4 b0 = *reinterpret_cast<const float4*>(&Bs[kk][tc * 8]);
            float4 b1 = *reinterpret_cast<const float4*>(&Bs[kk][tc * 8 + 4]);
            ULL bu[4];
            PACK2(bu[0], b0.x, b0.y); PACK2(bu[1], b0.z, b0.w);
            PACK2(bu[2], b1.x, b1.y); PACK2(bu[3], b1.z, b1.w);
            float ar[8] = {a0.x, a0.y, a0.z, a0.w, a1.x, a1.y, a1.z, a1.w};
#pragma unroll
            for (int r = 0; r < 8; r++) {
                ULL a2; PACK2(a2, ar[r], ar[r]);
                FMA2(acc[r][0], a2, bu[0]); FMA2(acc[r][1], a2, bu[1]);
                FMA2(acc[r][2], a2, bu[2]); FMA2(acc[r][3], a2, bu[3]);
            }
        }
        __syncthreads();
    }
    const float* bias = (blockIdx.y == 0) ? bk : (blockIdx.y == 1) ? bq : bv;
    const float qs = (blockIdx.y == 1) ? 0.08838834764831845f : 1.0f;
    float b8[8];
#pragma unroll
    for (int c = 0; c < 8; c++) b8[c] = bias[tc * 8 + c];
#pragma unroll
    for (int r = 0; r < 8; r++) {
        float o[8];
#pragma unroll
        for (int c = 0; c < 4; c++) { UNPACK2(o[2 * c], o[2 * c + 1], acc[r][c]); }
        float4 v0 = make_float4((o[0] + b8[0]) * qs, (o[1] + b8[1]) * qs,
                                (o[2] + b8[2]) * qs, (o[3] + b8[3]) * qs);
        float4 v1 = make_float4((o[4] + b8[4]) * qs, (o[5] + b8[5]) * qs,
                                (o[6] + b8[6]) * qs, (o[7] + b8[7]) * qs);
        float* cp = g_C + (m0 + tr * 8 + r) * 384 + n0 + tc * 8;
        *reinterpret_cast<float4*>(cp) = v0;
        *reinterpret_cast<float4*>(cp + 4) = v1;
    }
}

// ---- A2: avo/avd = tanh(cs + tail). grid 256, block 256 ----
__global__ void __launch_bounds__(256) tails_tanh(
    const float* __restrict__ actions, const float* __restrict__ policies) {
    __shared__ float actT[16][36], polT[16][36];   // [f][rr], 32 rows
    const int tid = threadIdx.x;
    const int r0 = blockIdx.x * 32;
#pragma unroll
    for (int w = 0; w < 2; w++) {
        int idx = tid + 256 * w;                   // 0..511
        int rr = idx >> 4, f = idx & 15;
        actT[f][rr] = actions[(r0 + rr) * 16 + f];
        polT[f][rr] = policies[(r0 + rr) * 16 + f];
    }
    __syncthreads();
    const int c = tid & 127, g = tid >> 7;         // 16 rows each
    float wv[16];
#pragma unroll
    for (int f = 0; f < 16; f++) wv[f] = g_Btail[f * 128 + c];
    for (int rr = g * 16; rr < g * 16 + 16; rr++) {
        float cs = g_C[(r0 + rr) * 384 + 256 + c];
        float ao = cs, ad = cs;
#pragma unroll
        for (int f = 0; f < 16; f++) {
            ao = fmaf(actT[f][rr], wv[f], ao);
            ad = fmaf(polT[f][rr], wv[f], ad);
        }
        float to, td; TANHA(to, ao); TANHA(td, ad);
        g_av[(r0 + rr) * 256 + c] = to;
        g_av[(r0 + rr) * 256 + 128 + c] = td;
    }
}

// ---- A3: [AW1|AdW1] = av @ W1T. grid (128, 2), block 128 ----
__global__ void __launch_bounds__(128) gemm_aw() {
    __shared__ float Ws[128][64];
    __shared__ float As[16][68];
    const int tid = threadIdx.x;
    const int m0 = blockIdx.x * 64, s = blockIdx.y;
    const int tr = tid >> 4, tc = tid & 15;        // 8 row-groups x 16 col-groups (4 cols)
#pragma unroll
    for (int w = 0; w < 16; w++) {
        int f4i = w * 128 + tid;                   // 0..2047
        int d = f4i >> 4, h = (f4i & 15) * 4;
        *reinterpret_cast<float4*>(&Ws[d][h]) =
            *reinterpret_cast<const float4*>(g_W1T + d * 64 + h);
    }
    ULL acc[8][2];
#pragma unroll
    for (int r = 0; r < 8; r++) { acc[r][0] = 0ull; acc[r][1] = 0ull; }

    for (int k0 = 0; k0 < 128; k0 += 16) {
#pragma unroll
        for (int w = 0; w < 2; w++) {
            int idx = tid * 2 + w;
            int row = idx >> 2, kq = (idx & 3) * 4;
            float4 v = *reinterpret_cast<const float4*>(g_av + (m0 + row) * 256 + s * 128 + k0 + kq);
            As[kq + 0][row] = v.x; As[kq + 1][row] = v.y;
            As[kq + 2][row] = v.z; As[kq + 3][row] = v.w;
        }
        __syncthreads();
#pragma unroll
        for (int kk = 0; kk < 16; kk++) {
            float4 a0 = *reinterpret_cast<const float4*>(&As[kk][tr * 8]);
            float4 a1 = *reinterpret_cast<const float4*>(&As[kk][tr * 8 + 4]);
            float4 b = *reinterpret_cast<const float4*>(&Ws[k0 + kk][tc * 4]);
            ULL bu[2];
            PACK2(bu[0], b.x, b.y); PACK2(bu[1], b.z, b.w);
            float ar[8] = {a0.x, a0.y, a0.z, a0.w, a1.x, a1.y, a1.z, a1.w};
#pragma unroll
            for (int r = 0; r < 8; r++) {
                ULL a2; PACK2(a2, ar[r], ar[r]);
                FMA2(acc[r][0], a2, bu[0]); FMA2(acc[r][1], a2, bu[1]);
            }
        }
        __syncthreads();
    }
#pragma unroll
    for (int r = 0; r < 8; r++) {
        float o[4];
        UNPACK2(o[0], o[1], acc[r][0]);
        UNPACK2(o[2], o[3], acc[r][1]);
        *reinterpret_cast<float4*>(g_aw + (m0 + tr * 8 + r) * 128 + s * 64 + tc * 4) =
            make_float4(o[0], o[1], o[2], o[3]);
    }
}

// ---- B: per-batch attention + output. grid 512, block 128 ----
__global__ void __launch_bounds__(128) attn_out(
    const float* __restrict__ W2, float* __restrict__ out, int out_size) {
    __shared__ float ks[16][128], qs[16][132];
    __shared__ float aw1[16][68], adw1[16][68];
    __shared__ float sw1[16][64];
    __shared__ float wt[16][17];
    __shared__ float w2s[64];
    const int tid = threadIdx.x;
    const int b = blockIdx.x, r0 = b * 16;

#pragma unroll
    for (int w = 0; w < 4; w++) {
        int f4i = w * 128 + tid;                   // 0..511
        int rr = f4i >> 5, c = (f4i & 31) * 4;
        *reinterpret_cast<float4*>(&ks[rr][c]) =
            *reinterpret_cast<const float4*>(g_C + (r0 + rr) * 384 + c);
        *reinterpret_cast<float4*>(&qs[rr][c]) =
            *reinterpret_cast<const float4*>(g_C + (r0 + rr) * 384 + 128 + c);
    }
#pragma unroll
    for (int w = 0; w < 4; w++) {
        int f4i = w * 128 + tid;
        int rr = f4i >> 5, c = (f4i & 31) * 4;
        float4 v = *reinterpret_cast<const float4*>(g_aw + (r0 + rr) * 128 + c);
        if (c < 64) *reinterpret_cast<float4*>(&aw1[rr][c]) = v;
        else        *reinterpret_cast<float4*>(&adw1[rr][c - 64]) = v;
    }
    if (tid < 64) w2s[tid] = W2[tid];
    __syncthreads();

    // scores + softmax over i (16-lane shfl groups)
#pragma unroll
    for (int s2 = 0; s2 < 2; s2++) {
        int id = tid + 128 * s2;
        int j = id >> 4, i = id & 15;
        const float4* qp = reinterpret_cast<const float4*>(&qs[i][0]);
        const float4* kp = reinterpret_cast<const float4*>(&ks[j][0]);
        float s0 = 0.f, s1 = 0.f, s2f = 0.f, s3 = 0.f;
#pragma unroll 8
        for (int d4 = 0; d4 < 32; d4++) {
            float4 qv = qp[d4], kv = kp[d4];
            s0 = fmaf(qv.x, kv.x, s0); s1 = fmaf(qv.y, kv.y, s1);
            s2f = fmaf(qv.z, kv.z, s2f); s3 = fmaf(qv.w, kv.w, s3);
        }
        float sc = (s0 + s1) + (s2f + s3);
        float m = sc;
#pragma unroll
        for (int o = 8; o; o >>= 1) m = fmaxf(m, __shfl_xor_sync(0xffffffffu, m, o));
        float e = __expf(sc - m);
        float sum = e;
#pragma unroll
        for (int o = 8; o; o >>= 1) sum += __shfl_xor_sync(0xffffffffu, sum, o);
        wt[j][i] = e / sum;
    }
    __syncthreads();

    // SW1[a,h] = sum_i wt[a,i] * AW1[i,h]
    {
        int h = tid & 63, g2 = tid >> 6, a0 = g2 * 8;
        float acc[8] = {};
#pragma unroll
        for (int i = 0; i < 16; i++) {
            float aw_ = aw1[i][h];
#pragma unroll
            for (int aa = 0; aa < 8; aa++)
                acc[aa] = fmaf(wt[a0 + aa][i], aw_, acc[aa]);
        }
#pragma unroll
        for (int aa = 0; aa < 8; aa++) sw1[a0 + aa][h] = acc[aa];
    }
    __syncthreads();

    // outputs
#pragma unroll
    for (int s2 = 0; s2 < 2; s2++) {
        int rem = tid + 128 * s2;
        int a = rem >> 4, j = rem & 15;
        float waj = wt[a][j];
        const float4* adp = reinterpret_cast<const float4*>(&adw1[j][0]);
        const float4* awp = reinterpret_cast<const float4*>(&aw1[j][0]);
        const float4* swp = reinterpret_cast<const float4*>(&sw1[a][0]);
        const float4* w2p = reinterpret_cast<const float4*>(&w2s[0]);
        float acc = 0.f;
#pragma unroll
        for (int h4 = 0; h4 < 16; h4++) {
            float4 ad = adp[h4], aw = awp[h4], swv = swp[h4], w2 = w2p[h4];
            float nf, v;
            nf = (swv.x + (ad.x - aw.x) * waj) * 0.0625f;
            v = nf > 0.f ? nf : 0.01f * nf; acc = fmaf(v, w2.x, acc);
            nf = (swv.y + (ad.y - aw.y) * waj) * 0.0625f;
            v = nf > 0.f ? nf : 0.01f * nf; acc = fmaf(v, w2.y, acc);
            nf = (swv.z + (ad.z - aw.z) * waj) * 0.0625f;
            v = nf > 0.f ? nf : 0.01f * nf; acc = fmaf(v, w2.z, acc);
            nf = (swv.w + (ad.w - aw.w) * waj) * 0.0625f;
            v = nf > 0.f ? nf : 0.01f * nf; acc = fmaf(v, w2.w, acc);
        }
        out[b * 256 + rem] = acc;                  // value[b, a, j]
        if (out_size >= 262144)                    // weight[b, j_out=a, i_out=j]
            out[131072 + b * 256 + rem] = wt[a][j];
    }
}

extern "C" void kernel_launch(void* const* d_in, const int* in_sizes, int n_in,
                              void* d_out, int out_size) {
    const float* states   = (const float*)d_in[0];
    const float* policies = (const float*)d_in[1];
    const float* actions  = (const float*)d_in[2];
    const float* Wk       = (const float*)d_in[3];
    const float* bk       = (const float*)d_in[4];
    const float* Wq       = (const float*)d_in[5];
    const float* bq       = (const float*)d_in[6];
    const float* Wv       = (const float*)d_in[7];
    const float* bv       = (const float*)d_in[8];
    const float* W1       = (const float*)d_in[9];
    const float* W2       = (const float*)d_in[10];
    float* out = (float*)d_out;

    prep<<<48, 256>>>(Wk, Wq, Wv, W1);
    gemm_kqc<<<dim3(128, 3), 128>>>(states, bk, bq, bv);
    tails_tanh<<<256, 256>>>(actions, policies);
    gemm_aw<<<dim3(128, 2), 128>>>();
    attn_out<<<512, 128>>>(W2, out, out_size);
}